// round 12
// baseline (speedup 1.0000x reference)
#include <cuda_runtime.h>
#include <cuda_fp16.h>

#define N_NODES 50000
#define N_EDGES 800000
#define NFEAT   256
#define NCLASS  64
#define NC2     (NCLASS / 2)     // 32 half2 per row
#define CAP     64               // per-dst padded capacity; Poisson(16), P(>64) ~ 1e-19

typedef unsigned long long ull;

// ---------------- scratch (no allocations allowed) ----------------
__device__ int     g_cur [N_NODES];           // fill cursor == in-degree (excl self)
__device__ float   g_dinv[N_NODES];
__device__ int     g_srci[N_NODES * CAP];     // staged src per slot (12.8 MB)
__device__ ull     g_rec [N_NODES * CAP];     // packed {w (hi 32), src (lo 32)} (25.6 MB)
__device__ __half2 g_h0  [N_NODES * NC2];     // fp16 feature buffers
__device__ __half2 g_h1  [N_NODES * NC2];

// ---------------- streams/events for fork-join capture ----------------
static cudaStream_t g_s1;
static cudaEvent_t  g_evFork, g_evJoin;
static struct SideInit {
    SideInit() {
        cudaStreamCreateWithFlags(&g_s1, cudaStreamNonBlocking);
        cudaEventCreateWithFlags(&g_evFork, cudaEventDisableTiming);
        cudaEventCreateWithFlags(&g_evJoin, cudaEventDisableTiming);
    }
} g_sideInit;

// ---------------- f32x2 packed helpers (GEMM) ----------------
__device__ __forceinline__ ull pack2(float x, float y) {
    ull d;
    asm("mov.b64 %0, {%1, %2};" : "=l"(d) : "f"(x), "f"(y));
    return d;
}
__device__ __forceinline__ ull fma2(ull a, ull b, ull c) {
    ull d;
    asm("fma.rn.f32x2 %0, %1, %2, %3;" : "=l"(d) : "l"(a), "l"(b), "l"(c));
    return d;
}
__device__ __forceinline__ void unpack2(ull d, float& x, float& y) {
    asm("mov.b64 {%0, %1}, %2;" : "=f"(x), "=f"(y) : "l"(d));
}

// ---------------- padded-bucket build (fill IS the histogram; no scans) ----------------
__global__ void fill_kernel(const int* __restrict__ ei) {
    int e = blockIdx.x * blockDim.x + threadIdx.x;
    if (e < N_EDGES) {
        unsigned s = (unsigned)ei[e];
        unsigned d = (unsigned)ei[N_EDGES + e];
        if (s < N_NODES && d < N_NODES) {
            int pos = atomicAdd(&g_cur[d], 1);
            if (pos < CAP) g_srci[d * CAP + pos] = (int)s;
        }
    }
}

__global__ void dinv_kernel() {
    int i = blockIdx.x * blockDim.x + threadIdx.x;
    if (i < N_NODES) g_dinv[i] = rsqrtf((float)(g_cur[i] + 1));   // +1 self loop
}

// slot-parallel pack: one thread per (node, slot)
__global__ void pack_kernel() {
    int idx  = blockIdx.x * blockDim.x + threadIdx.x;
    if (idx >= N_NODES * CAP) return;
    int node = idx >> 6;          // /CAP
    int slot = idx & (CAP - 1);
    int deg  = g_cur[node];
    if (deg > CAP) deg = CAP;
    if (slot >= deg) return;
    int s = g_srci[idx];
    float w = g_dinv[s] * g_dinv[node];
    g_rec[idx] = ((ull)__float_as_uint(w) << 32) | (ull)(unsigned)s;
}

// ---------------- GEMM: Y0[50000,64] = x[50000,256] @ W[256,64] -> half2 ----------------
__global__ void gemm_kernel(const float* __restrict__ x,
                            const float* __restrict__ W,
                            __half2* __restrict__ y) {
    __shared__ float xs[64][36];   // [row][k], padded for float4 stores
    __shared__ ull   ws2[32][34];  // [k][col-pair], 16B-aligned rows

    int t  = threadIdx.x;
    int tx = t & 15;               // col group (cols tx*4 .. tx*4+3)
    int ty = t >> 4;               // row group (rows ty*4 .. ty*4+3)
    int row0 = blockIdx.x * 64;

    ull acc[4][2];
#pragma unroll
    for (int r = 0; r < 4; r++) { acc[r][0] = 0ULL; acc[r][1] = 0ULL; }

    for (int k0 = 0; k0 < NFEAT; k0 += 32) {
#pragma unroll
        for (int i = 0; i < 2; i++) {
            int idx = t + i * 256;
            int r   = idx >> 3;
            int kq  = idx & 7;
            int row = row0 + r;
            float4 v = make_float4(0.f, 0.f, 0.f, 0.f);
            if (row < N_NODES)
                v = *(const float4*)&x[row * NFEAT + k0 + kq * 4];
            *(float4*)&xs[r][kq * 4] = v;
        }
#pragma unroll
        for (int i = 0; i < 2; i++) {
            int idx = t + i * 256;
            int kk  = idx >> 4;
            int cq  = idx & 15;
            float4 v = *(const float4*)&W[(k0 + kk) * NCLASS + cq * 4];
            ws2[kk][cq * 2 + 0] = pack2(v.x, v.y);
            ws2[kk][cq * 2 + 1] = pack2(v.z, v.w);
        }
        __syncthreads();

#pragma unroll
        for (int kk = 0; kk < 32; kk++) {
            ulonglong2 b = *(const ulonglong2*)&ws2[kk][tx * 2];
#pragma unroll
            for (int r = 0; r < 4; r++) {
                float a = xs[ty * 4 + r][kk];
                ull ap = pack2(a, a);
                acc[r][0] = fma2(ap, b.x, acc[r][0]);
                acc[r][1] = fma2(ap, b.y, acc[r][1]);
            }
        }
        __syncthreads();
    }

#pragma unroll
    for (int r = 0; r < 4; r++) {
        int row = row0 + ty * 4 + r;
        if (row < N_NODES) {
            float4 o;
            unpack2(acc[r][0], o.x, o.y);
            unpack2(acc[r][1], o.z, o.w);
            __half2 h0 = __floats2half2_rn(o.x, o.y);
            __half2 h1 = __floats2half2_rn(o.z, o.w);
            __half2* yp = y + row * NC2 + tx * 2;
            yp[0] = h0;
            yp[1] = h1;
        }
    }
}

// ---------------- pull-based hop: lane-cooperative record load + shfl broadcast ----------------
// Per node: ONE coalesced LDG loads up to 32 records across lanes; each record is
// broadcast via shfl, making all row-gathers independent (full-degree MLP).
__device__ __forceinline__ float2 hop_accum(const __half2* __restrict__ xin,
                                            int node, int lane) {
    int deg = g_cur[node];
    if (deg > CAP) deg = CAP;
    int beg = node * CAP;
    float di = g_dinv[node];
    float w0 = di * di;

    float2 vf = __half22float2(xin[node * NC2 + lane]);
    float2 acc;
    acc.x = w0 * vf.x;
    acc.y = w0 * vf.y;

    // cooperative record load: lane q holds record q (one 128-256B coalesced LDG)
    ull myrec = (lane < deg) ? g_rec[beg + lane] : 0ULL;

    int m = deg < 32 ? deg : 32;
    int q = 0;
    for (; q + 8 <= m; q += 8) {
        ull  r[8];
        float2 u[8];
#pragma unroll
        for (int k = 0; k < 8; k++) r[k] = __shfl_sync(0xFFFFFFFFu, myrec, q + k);
#pragma unroll
        for (int k = 0; k < 8; k++)
            u[k] = __half22float2(xin[((int)(unsigned)r[k]) * NC2 + lane]);
#pragma unroll
        for (int k = 0; k < 8; k++) {
            float wk = __uint_as_float((unsigned)(r[k] >> 32));
            acc.x += wk * u[k].x;
            acc.y += wk * u[k].y;
        }
    }
    for (; q < m; q++) {
        ull r0 = __shfl_sync(0xFFFFFFFFu, myrec, q);
        float2 u0 = __half22float2(xin[((int)(unsigned)r0) * NC2 + lane]);
        float w1 = __uint_as_float((unsigned)(r0 >> 32));
        acc.x += w1 * u0.x;
        acc.y += w1 * u0.y;
    }
    // rare tail: deg > 32 (Poisson(16), ~1e-4 of nodes)
    for (int j = beg + 32; j < beg + deg; j++) {
        ull r0 = g_rec[j];
        float2 u0 = __half22float2(xin[((int)(unsigned)r0) * NC2 + lane]);
        float w1 = __uint_as_float((unsigned)(r0 >> 32));
        acc.x += w1 * u0.x;
        acc.y += w1 * u0.y;
    }
    return acc;
}

__global__ void hop_h_kernel(const __half2* __restrict__ xin,
                             __half2* __restrict__ yout) {
    int gtid = blockIdx.x * blockDim.x + threadIdx.x;
    int node = gtid >> 5;
    int lane = threadIdx.x & 31;
    if (node >= N_NODES) return;
    float2 acc = hop_accum(xin, node, lane);
    yout[node * NC2 + lane] = __floats2half2_rn(acc.x, acc.y);
}

__global__ void hop_f_kernel(const __half2* __restrict__ xin,
                             float* __restrict__ yout,
                             const float* __restrict__ bias) {
    int gtid = blockIdx.x * blockDim.x + threadIdx.x;
    int node = gtid >> 5;
    int lane = threadIdx.x & 31;
    if (node >= N_NODES) return;
    float2 acc = hop_accum(xin, node, lane);
    acc.x += bias[lane * 2];
    acc.y += bias[lane * 2 + 1];
    *(float2*)(yout + node * NCLASS + lane * 2) = acc;
}

// ---------------- launch ----------------
extern "C" void kernel_launch(void* const* d_in, const int* in_sizes, int n_in,
                              void* d_out, int out_size) {
    const float* x  = (const float*)d_in[0];
    const int*   ei = (const int*)d_in[1];
    const float* W  = (const float*)d_in[2];
    const float* b  = (const float*)d_in[3];
    float* out = (float*)d_out;

    __half2 *h0, *h1;
    cudaGetSymbolAddress((void**)&h0, g_h0);
    cudaGetSymbolAddress((void**)&h1, g_h1);
    int* cur_ptr;
    cudaGetSymbolAddress((void**)&cur_ptr, g_cur);

    const int T = 256;
    int gE = (N_EDGES + T - 1) / T;
    int gN = (N_NODES + T - 1) / T;
    int gS = (N_NODES * CAP + T - 1) / T;     // slot-parallel pack
    int gW = (N_NODES * 32 + T - 1) / T;      // warp per node
    int gG = (N_NODES + 63) / 64;             // gemm blocks

    // Fork: GEMM (x, W only) on side stream, concurrent with bucket build (edge_index only).
    cudaEventRecord(g_evFork, 0);
    cudaStreamWaitEvent(g_s1, g_evFork, 0);
    gemm_kernel<<<gG, T, 0, g_s1>>>(x, W, h0);
    cudaEventRecord(g_evJoin, g_s1);

    // Padded-bucket build: memset -> fill (= histogram) -> dinv -> slot-parallel pack
    cudaMemsetAsync(cur_ptr, 0, N_NODES * sizeof(int), 0);
    fill_kernel<<<gE, T>>>(ei);
    dinv_kernel<<<gN, T>>>();
    pack_kernel<<<gS, T>>>();

    // Join: hops need both h0 (GEMM) and packed records
    cudaStreamWaitEvent(0, g_evJoin, 0);

    hop_h_kernel<<<gW, T>>>(h0, h1);
    hop_h_kernel<<<gW, T>>>(h1, h0);
    hop_f_kernel<<<gW, T>>>(h0, out, b);
}

// round 13
// speedup vs baseline: 1.1745x; 1.1745x over previous
#include <cuda_runtime.h>
#include <cuda_fp16.h>

#define N_NODES 50000
#define N_EDGES 800000
#define NFEAT   256
#define NCLASS  64
#define NC2     (NCLASS / 2)     // 32 half2 per row
#define CAP     64               // per-dst padded capacity; Poisson(16), P(>64) ~ 1e-19

typedef unsigned long long ull;

// ---------------- scratch (no allocations allowed) ----------------
__device__ int     g_cur [N_NODES];           // fill cursor == in-degree (excl self)
__device__ float   g_dinv[N_NODES];
__device__ int     g_srci[N_NODES * CAP];     // padded buckets of src indices (12.8 MB)
__device__ __half2 g_h0  [N_NODES * NC2];     // fp16 feature buffers (scaled space)
__device__ __half2 g_h1  [N_NODES * NC2];

// ---------------- streams/events for fork-join capture ----------------
static cudaStream_t g_s1;
static cudaEvent_t  g_evFork, g_evJoin;
static struct SideInit {
    SideInit() {
        cudaStreamCreateWithFlags(&g_s1, cudaStreamNonBlocking);
        cudaEventCreateWithFlags(&g_evFork, cudaEventDisableTiming);
        cudaEventCreateWithFlags(&g_evJoin, cudaEventDisableTiming);
    }
} g_sideInit;

// ---------------- f32x2 packed helpers (GEMM) ----------------
__device__ __forceinline__ ull pack2(float x, float y) {
    ull d;
    asm("mov.b64 %0, {%1, %2};" : "=l"(d) : "f"(x), "f"(y));
    return d;
}
__device__ __forceinline__ ull fma2(ull a, ull b, ull c) {
    ull d;
    asm("fma.rn.f32x2 %0, %1, %2, %3;" : "=l"(d) : "l"(a), "l"(b), "l"(c));
    return d;
}
__device__ __forceinline__ void unpack2(ull d, float& x, float& y) {
    asm("mov.b64 {%0, %1}, %2;" : "=f"(x), "=f"(y) : "l"(d));
}

// ---------------- padded-bucket build (fill IS the histogram; no scans, no pack) ----------------
__global__ void fill_kernel(const int* __restrict__ ei) {
    int e = blockIdx.x * blockDim.x + threadIdx.x;
    if (e < N_EDGES) {
        unsigned s = (unsigned)ei[e];
        unsigned d = (unsigned)ei[N_EDGES + e];
        if (s < N_NODES && d < N_NODES) {
            int pos = atomicAdd(&g_cur[d], 1);
            if (pos < CAP) g_srci[d * CAP + pos] = (int)s;
        }
    }
}

__global__ void dinv_kernel() {
    int i = blockIdx.x * blockDim.x + threadIdx.x;
    if (i < N_NODES) g_dinv[i] = rsqrtf((float)(g_cur[i] + 1));   // +1 self loop
}

// ---------------- GEMM: Y0[50000,64] = x[50000,256] @ W[256,64] -> half2 ----------------
__global__ void gemm_kernel(const float* __restrict__ x,
                            const float* __restrict__ W,
                            __half2* __restrict__ y) {
    __shared__ float xs[64][36];   // [row][k], padded for float4 stores
    __shared__ ull   ws2[32][34];  // [k][col-pair], 16B-aligned rows

    int t  = threadIdx.x;
    int tx = t & 15;               // col group (cols tx*4 .. tx*4+3)
    int ty = t >> 4;               // row group (rows ty*4 .. ty*4+3)
    int row0 = blockIdx.x * 64;

    ull acc[4][2];
#pragma unroll
    for (int r = 0; r < 4; r++) { acc[r][0] = 0ULL; acc[r][1] = 0ULL; }

    for (int k0 = 0; k0 < NFEAT; k0 += 32) {
#pragma unroll
        for (int i = 0; i < 2; i++) {
            int idx = t + i * 256;
            int r   = idx >> 3;
            int kq  = idx & 7;
            int row = row0 + r;
            float4 v = make_float4(0.f, 0.f, 0.f, 0.f);
            if (row < N_NODES)
                v = *(const float4*)&x[row * NFEAT + k0 + kq * 4];
            *(float4*)&xs[r][kq * 4] = v;
        }
#pragma unroll
        for (int i = 0; i < 2; i++) {
            int idx = t + i * 256;
            int kk  = idx >> 4;
            int cq  = idx & 15;
            float4 v = *(const float4*)&W[(k0 + kk) * NCLASS + cq * 4];
            ws2[kk][cq * 2 + 0] = pack2(v.x, v.y);
            ws2[kk][cq * 2 + 1] = pack2(v.z, v.w);
        }
        __syncthreads();

#pragma unroll
        for (int kk = 0; kk < 32; kk++) {
            ulonglong2 b = *(const ulonglong2*)&ws2[kk][tx * 2];
#pragma unroll
            for (int r = 0; r < 4; r++) {
                float a = xs[ty * 4 + r][kk];
                ull ap = pack2(a, a);
                acc[r][0] = fma2(ap, b.x, acc[r][0]);
                acc[r][1] = fma2(ap, b.y, acc[r][1]);
            }
        }
        __syncthreads();
    }

#pragma unroll
    for (int r = 0; r < 4; r++) {
        int row = row0 + ty * 4 + r;
        if (row < N_NODES) {
            float4 o;
            unpack2(acc[r][0], o.x, o.y);
            unpack2(acc[r][1], o.z, o.w);
            __half2 h0 = __floats2half2_rn(o.x, o.y);
            __half2 h1 = __floats2half2_rn(o.z, o.w);
            __half2* yp = y + row * NC2 + tx * 2;
            yp[0] = h0;
            yp[1] = h1;
        }
    }
}

// ---------------- scale into D^-1/2 space: u0 = dinv * y0 ----------------
__global__ void scale_kernel(__half2* __restrict__ buf) {
    int idx = blockIdx.x * blockDim.x + threadIdx.x;
    if (idx >= N_NODES * NC2) return;
    int node = idx >> 5;
    float di = g_dinv[node];
    float2 v = __half22float2(buf[idx]);
    buf[idx] = __floats2half2_rn(di * v.x, di * v.y);
}

// ---------------- unweighted gather-sum: acc = u[node] + sum_in u[src] ----------------
__device__ __forceinline__ float2 hop_accum(const __half2* __restrict__ xin,
                                            int node, int lane) {
    int deg = g_cur[node];
    if (deg > CAP) deg = CAP;
    const int* bkt = g_srci + node * CAP;     // 256B-aligned bucket

    float2 acc = __half22float2(xin[node * NC2 + lane]);   // self term

    int j = 0;
    for (; j + 8 <= deg; j += 8) {
        int4 a = *(const int4*)(bkt + j);      // warp-uniform broadcast, 4 srcs
        int4 c = *(const int4*)(bkt + j + 4);
        float2 u0 = __half22float2(xin[a.x * NC2 + lane]);
        float2 u1 = __half22float2(xin[a.y * NC2 + lane]);
        float2 u2 = __half22float2(xin[a.z * NC2 + lane]);
        float2 u3 = __half22float2(xin[a.w * NC2 + lane]);
        float2 u4 = __half22float2(xin[c.x * NC2 + lane]);
        float2 u5 = __half22float2(xin[c.y * NC2 + lane]);
        float2 u6 = __half22float2(xin[c.z * NC2 + lane]);
        float2 u7 = __half22float2(xin[c.w * NC2 + lane]);
        acc.x += u0.x + u1.x + u2.x + u3.x + u4.x + u5.x + u6.x + u7.x;
        acc.y += u0.y + u1.y + u2.y + u3.y + u4.y + u5.y + u6.y + u7.y;
    }
    if (j + 4 <= deg) {
        int4 a = *(const int4*)(bkt + j);
        float2 u0 = __half22float2(xin[a.x * NC2 + lane]);
        float2 u1 = __half22float2(xin[a.y * NC2 + lane]);
        float2 u2 = __half22float2(xin[a.z * NC2 + lane]);
        float2 u3 = __half22float2(xin[a.w * NC2 + lane]);
        acc.x += u0.x + u1.x + u2.x + u3.x;
        acc.y += u0.y + u1.y + u2.y + u3.y;
        j += 4;
    }
    for (; j < deg; j++) {
        int s = bkt[j];
        float2 u0 = __half22float2(xin[s * NC2 + lane]);
        acc.x += u0.x;
        acc.y += u0.y;
    }
    return acc;
}

// middle hop: u' = dinv^2 * (u + sum_in u[src])
__global__ void hop_h_kernel(const __half2* __restrict__ xin,
                             __half2* __restrict__ yout) {
    int gtid = blockIdx.x * blockDim.x + threadIdx.x;
    int node = gtid >> 5;
    int lane = threadIdx.x & 31;
    if (node >= N_NODES) return;
    float2 acc = hop_accum(xin, node, lane);
    float di = g_dinv[node];
    float dd = di * di;
    yout[node * NC2 + lane] = __floats2half2_rn(dd * acc.x, dd * acc.y);
}

// final hop: out = dinv * (u + sum_in u[src]) + bias
__global__ void hop_f_kernel(const __half2* __restrict__ xin,
                             float* __restrict__ yout,
                             const float* __restrict__ bias) {
    int gtid = blockIdx.x * blockDim.x + threadIdx.x;
    int node = gtid >> 5;
    int lane = threadIdx.x & 31;
    if (node >= N_NODES) return;
    float2 acc = hop_accum(xin, node, lane);
    float di = g_dinv[node];
    acc.x = di * acc.x + bias[lane * 2];
    acc.y = di * acc.y + bias[lane * 2 + 1];
    *(float2*)(yout + node * NCLASS + lane * 2) = acc;
}

// ---------------- launch ----------------
extern "C" void kernel_launch(void* const* d_in, const int* in_sizes, int n_in,
                              void* d_out, int out_size) {
    const float* x  = (const float*)d_in[0];
    const int*   ei = (const int*)d_in[1];
    const float* W  = (const float*)d_in[2];
    const float* b  = (const float*)d_in[3];
    float* out = (float*)d_out;

    __half2 *h0, *h1;
    cudaGetSymbolAddress((void**)&h0, g_h0);
    cudaGetSymbolAddress((void**)&h1, g_h1);
    int* cur_ptr;
    cudaGetSymbolAddress((void**)&cur_ptr, g_cur);

    const int T = 256;
    int gE = (N_EDGES + T - 1) / T;
    int gN = (N_NODES + T - 1) / T;
    int gW = (N_NODES * 32 + T - 1) / T;      // warp per node / elementwise over rows
    int gG = (N_NODES + 63) / 64;             // gemm blocks

    // Fork: GEMM (x, W only) on side stream, concurrent with bucket build (edge_index only).
    cudaEventRecord(g_evFork, 0);
    cudaStreamWaitEvent(g_s1, g_evFork, 0);
    gemm_kernel<<<gG, T, 0, g_s1>>>(x, W, h0);
    cudaEventRecord(g_evJoin, g_s1);

    // Build: memset -> fill (= histogram) -> dinv.  (No scans, no pack.)
    cudaMemsetAsync(cur_ptr, 0, N_NODES * sizeof(int), 0);
    fill_kernel<<<gE, T>>>(ei);
    dinv_kernel<<<gN, T>>>();

    // Join: scale needs h0 (GEMM) + dinv (build)
    cudaStreamWaitEvent(0, g_evJoin, 0);
    scale_kernel<<<gW, T>>>(h0);              // u0 = dinv * y0

    hop_h_kernel<<<gW, T>>>(h0, h1);          // u1 = D^-1 (A+I) u0
    hop_h_kernel<<<gW, T>>>(h1, h0);          // u2 = D^-1 (A+I) u1
    hop_f_kernel<<<gW, T>>>(h0, out, b);      // out = D^-1/2 (A+I) u2 + b
}

// round 17
// speedup vs baseline: 1.2869x; 1.0957x over previous
#include <cuda_runtime.h>
#include <cuda_fp16.h>

#define N_NODES 50000
#define N_EDGES 800000
#define NFEAT   256
#define NCLASS  64
#define NC2     (NCLASS / 2)     // 32 half2 per row
#define NCU     16               // 16 ull (8B) per row
#define CAP     64               // per-dst padded capacity; Poisson(16), P(>64) ~ 1e-19

typedef unsigned long long ull;

// ---------------- scratch (no allocations allowed) ----------------
__device__ int     g_cur [N_NODES];           // fill cursor == in-degree (excl self)
__device__ float   g_dinv[N_NODES];
__device__ int     g_srci[N_NODES * CAP];     // padded buckets of src indices (12.8 MB)
__device__ __half2 g_h0  [N_NODES * NC2];     // fp16 feature buffers (scaled space)
__device__ __half2 g_h1  [N_NODES * NC2];

// ---------------- streams/events for fork-join capture ----------------
static cudaStream_t g_s1;
static cudaEvent_t  g_evFork, g_evJoin;
static struct SideInit {
    SideInit() {
        cudaStreamCreateWithFlags(&g_s1, cudaStreamNonBlocking);
        cudaEventCreateWithFlags(&g_evFork, cudaEventDisableTiming);
        cudaEventCreateWithFlags(&g_evJoin, cudaEventDisableTiming);
    }
} g_sideInit;

// ---------------- f32x2 packed helpers (GEMM) ----------------
__device__ __forceinline__ ull pack2(float x, float y) {
    ull d;
    asm("mov.b64 %0, {%1, %2};" : "=l"(d) : "f"(x), "f"(y));
    return d;
}
__device__ __forceinline__ ull fma2(ull a, ull b, ull c) {
    ull d;
    asm("fma.rn.f32x2 %0, %1, %2, %3;" : "=l"(d) : "l"(a), "l"(b), "l"(c));
    return d;
}
__device__ __forceinline__ void unpack2(ull d, float& x, float& y) {
    asm("mov.b64 {%0, %1}, %2;" : "=f"(x), "=f"(y) : "l"(d));
}

// unpack one 8-byte chunk (2 half2) and accumulate into float4
__device__ __forceinline__ void acc_row(float4& acc, ull v) {
    union { ull u; __half2 h[2]; } cv;
    cv.u = v;
    float2 a = __half22float2(cv.h[0]);
    float2 b = __half22float2(cv.h[1]);
    acc.x += a.x; acc.y += a.y; acc.z += b.x; acc.w += b.y;
}

// ---------------- padded-bucket build (fill IS the histogram) ----------------
__global__ void fill_kernel(const int* __restrict__ ei) {
    int e = blockIdx.x * blockDim.x + threadIdx.x;
    if (e < N_EDGES) {
        unsigned s = (unsigned)ei[e];
        unsigned d = (unsigned)ei[N_EDGES + e];
        if (s < N_NODES && d < N_NODES) {
            int pos = atomicAdd(&g_cur[d], 1);
            if (pos < CAP) g_srci[d * CAP + pos] = (int)s;
        }
    }
}

__global__ void dinv_kernel() {
    int i = blockIdx.x * blockDim.x + threadIdx.x;
    if (i < N_NODES) g_dinv[i] = rsqrtf((float)(g_cur[i] + 1));   // +1 self loop
}

// ---------------- GEMM: Y0[50000,64] = x[50000,256] @ W[256,64] -> half2 ----------------
__global__ void gemm_kernel(const float* __restrict__ x,
                            const float* __restrict__ W,
                            __half2* __restrict__ y) {
    __shared__ float xs[64][36];   // [row][k], padded for float4 stores
    __shared__ ull   ws2[32][34];  // [k][col-pair], 16B-aligned rows

    int t  = threadIdx.x;
    int tx = t & 15;               // col group (cols tx*4 .. tx*4+3)
    int ty = t >> 4;               // row group (rows ty*4 .. ty*4+3)
    int row0 = blockIdx.x * 64;

    ull acc[4][2];
#pragma unroll
    for (int r = 0; r < 4; r++) { acc[r][0] = 0ULL; acc[r][1] = 0ULL; }

    for (int k0 = 0; k0 < NFEAT; k0 += 32) {
#pragma unroll
        for (int i = 0; i < 2; i++) {
            int idx = t + i * 256;
            int r   = idx >> 3;
            int kq  = idx & 7;
            int row = row0 + r;
            float4 v = make_float4(0.f, 0.f, 0.f, 0.f);
            if (row < N_NODES)
                v = *(const float4*)&x[row * NFEAT + k0 + kq * 4];
            *(float4*)&xs[r][kq * 4] = v;
        }
#pragma unroll
        for (int i = 0; i < 2; i++) {
            int idx = t + i * 256;
            int kk  = idx >> 4;
            int cq  = idx & 15;
            float4 v = *(const float4*)&W[(k0 + kk) * NCLASS + cq * 4];
            ws2[kk][cq * 2 + 0] = pack2(v.x, v.y);
            ws2[kk][cq * 2 + 1] = pack2(v.z, v.w);
        }
        __syncthreads();

#pragma unroll
        for (int kk = 0; kk < 32; kk++) {
            ulonglong2 b = *(const ulonglong2*)&ws2[kk][tx * 2];
#pragma unroll
            for (int r = 0; r < 4; r++) {
                float a = xs[ty * 4 + r][kk];
                ull ap = pack2(a, a);
                acc[r][0] = fma2(ap, b.x, acc[r][0]);
                acc[r][1] = fma2(ap, b.y, acc[r][1]);
            }
        }
        __syncthreads();
    }

#pragma unroll
    for (int r = 0; r < 4; r++) {
        int row = row0 + ty * 4 + r;
        if (row < N_NODES) {
            float4 o;
            unpack2(acc[r][0], o.x, o.y);
            unpack2(acc[r][1], o.z, o.w);
            __half2 h0 = __floats2half2_rn(o.x, o.y);
            __half2 h1 = __floats2half2_rn(o.z, o.w);
            __half2* yp = y + row * NC2 + tx * 2;
            yp[0] = h0;
            yp[1] = h1;
        }
    }
}

// ---------------- scale into D^-1/2 space: u0 = dinv * y0 (int4-wide) ----------------
__global__ void scale_kernel(int4* __restrict__ buf) {
    int idx = blockIdx.x * blockDim.x + threadIdx.x;   // one int4 = 4 half2 = 8 halves
    if (idx >= N_NODES * 8) return;
    int node = idx >> 3;
    float di = g_dinv[node];
    int4 v = buf[idx];
    union { int4 i; __half2 h[4]; } cv;
    cv.i = v;
#pragma unroll
    for (int k = 0; k < 4; k++) {
        float2 f = __half22float2(cv.h[k]);
        cv.h[k] = __floats2half2_rn(di * f.x, di * f.y);
    }
    buf[idx] = cv.i;
}

// ---------------- unweighted gather-sum, 16 lanes per node ----------------
// lane16 covers 8 bytes (2 half2 = 4 values) of the 128B row -> one LDG.64,
// full row per half-warp, two independent nodes per warp (2x gather MLP).
__device__ __forceinline__ float4 hop_accum(const ull* __restrict__ rows,
                                            int node, int lane16) {
    int deg = g_cur[node];
    if (deg > CAP) deg = CAP;
    const int* bkt = g_srci + node * CAP;     // 256B-aligned bucket

    float4 acc = make_float4(0.f, 0.f, 0.f, 0.f);
    acc_row(acc, rows[node * NCU + lane16]);  // self term

    int j = 0;
    for (; j + 8 <= deg; j += 8) {
        int4 a = *(const int4*)(bkt + j);     // half-warp-uniform broadcast
        int4 c = *(const int4*)(bkt + j + 4);
        ull u0 = rows[a.x * NCU + lane16];
        ull u1 = rows[a.y * NCU + lane16];
        ull u2 = rows[a.z * NCU + lane16];
        ull u3 = rows[a.w * NCU + lane16];
        ull u4 = rows[c.x * NCU + lane16];
        ull u5 = rows[c.y * NCU + lane16];
        ull u6 = rows[c.z * NCU + lane16];
        ull u7 = rows[c.w * NCU + lane16];
        acc_row(acc, u0); acc_row(acc, u1); acc_row(acc, u2); acc_row(acc, u3);
        acc_row(acc, u4); acc_row(acc, u5); acc_row(acc, u6); acc_row(acc, u7);
    }
    if (j + 4 <= deg) {
        int4 a = *(const int4*)(bkt + j);
        ull u0 = rows[a.x * NCU + lane16];
        ull u1 = rows[a.y * NCU + lane16];
        ull u2 = rows[a.z * NCU + lane16];
        ull u3 = rows[a.w * NCU + lane16];
        acc_row(acc, u0); acc_row(acc, u1); acc_row(acc, u2); acc_row(acc, u3);
        j += 4;
    }
    for (; j < deg; j++) {
        acc_row(acc, rows[bkt[j] * NCU + lane16]);
    }
    return acc;
}

// middle hop: u' = dinv^2 * (u + sum_in u[src])
__global__ void hop_h_kernel(const ull* __restrict__ xin,
                             ull* __restrict__ yout) {
    int gtid = blockIdx.x * blockDim.x + threadIdx.x;
    int node = gtid >> 4;
    int lane16 = threadIdx.x & 15;
    if (node >= N_NODES) return;
    float4 acc = hop_accum(xin, node, lane16);
    float di = g_dinv[node];
    float dd = di * di;
    union { ull u; __half2 h[2]; } cv;
    cv.h[0] = __floats2half2_rn(dd * acc.x, dd * acc.y);
    cv.h[1] = __floats2half2_rn(dd * acc.z, dd * acc.w);
    yout[node * NCU + lane16] = cv.u;
}

// final hop: out = dinv * (u + sum_in u[src]) + bias
__global__ void hop_f_kernel(const ull* __restrict__ xin,
                             float* __restrict__ yout,
                             const float* __restrict__ bias) {
    int gtid = blockIdx.x * blockDim.x + threadIdx.x;
    int node = gtid >> 4;
    int lane16 = threadIdx.x & 15;
    if (node >= N_NODES) return;
    float4 acc = hop_accum(xin, node, lane16);
    float di = g_dinv[node];
    float4 bb = *(const float4*)(bias + lane16 * 4);
    acc.x = di * acc.x + bb.x;
    acc.y = di * acc.y + bb.y;
    acc.z = di * acc.z + bb.z;
    acc.w = di * acc.w + bb.w;
    *(float4*)(yout + node * NCLASS + lane16 * 4) = acc;
}

// ---------------- launch ----------------
extern "C" void kernel_launch(void* const* d_in, const int* in_sizes, int n_in,
                              void* d_out, int out_size) {
    const float* x  = (const float*)d_in[0];
    const int*   ei = (const int*)d_in[1];
    const float* W  = (const float*)d_in[2];
    const float* b  = (const float*)d_in[3];
    float* out = (float*)d_out;

    __half2 *h0, *h1;
    cudaGetSymbolAddress((void**)&h0, g_h0);
    cudaGetSymbolAddress((void**)&h1, g_h1);
    int* cur_ptr;
    cudaGetSymbolAddress((void**)&cur_ptr, g_cur);

    const int T = 256;
    int gE = (N_EDGES + T - 1) / T;
    int gN = (N_NODES + T - 1) / T;
    int gS = (N_NODES * 8 + T - 1) / T;       // scale: one int4 per thread
    int gH = (N_NODES * 16 + T - 1) / T;      // hops: 16 lanes per node
    int gG = (N_NODES + 63) / 64;             // gemm blocks

    // Fork: GEMM (x, W only) on side stream, concurrent with bucket build (edge_index only).
    cudaEventRecord(g_evFork, 0);
    cudaStreamWaitEvent(g_s1, g_evFork, 0);
    gemm_kernel<<<gG, T, 0, g_s1>>>(x, W, h0);
    cudaEventRecord(g_evJoin, g_s1);

    // Build: memset -> fill (= histogram) -> dinv.  (No scans, no pack.)
    cudaMemsetAsync(cur_ptr, 0, N_NODES * sizeof(int), 0);
    fill_kernel<<<gE, T>>>(ei);
    dinv_kernel<<<gN, T>>>();

    // Join: scale needs h0 (GEMM) + dinv (build)
    cudaStreamWaitEvent(0, g_evJoin, 0);
    scale_kernel<<<gS, T>>>((int4*)h0);                   // u0 = dinv * y0

    hop_h_kernel<<<gH, T>>>((const ull*)h0, (ull*)h1);    // u1 = D^-1 (A+I) u0
    hop_h_kernel<<<gH, T>>>((const ull*)h1, (ull*)h0);    // u2 = D^-1 (A+I) u1
    hop_f_kernel<<<gH, T>>>((const ull*)h0, out, b);      // out = D^-1/2 (A+I) u2 + b
}